// round 16
// baseline (speedup 1.0000x reference)
#include <cuda_runtime.h>
#include <cuda_bf16.h>
#include <cuda_fp16.h>
#include <cstdint>

#define BATCH 4
#define S_LEN 2048
#define NH    16
#define DK    64
#define DM    1024
#define MT    (BATCH*S_LEN)
#define BHSZ  ((size_t)BATCH * NH * S_LEN * DK)
#define LOG2E 1.4426950408889634f

__device__ __nv_bfloat16 g_h_hi[MT * DM];
__device__ __nv_bfloat16 g_h_lo[MT * DM];
__device__ __half        g_h_f[MT * DM];
__device__ __nv_bfloat16 g_wt_hi[2 * DM * DM];
__device__ __nv_bfloat16 g_wt_lo[2 * DM * DM];
__device__ __half        g_wv_hi[DM * DM];
__device__ __half        g_wv_lo[DM * DM];
__device__ __half        g_wo_f[DM * DM];
__device__ __nv_bfloat16 g_qh[BHSZ], g_ql[BHSZ];
__device__ __nv_bfloat16 g_kh[BHSZ], g_kl[BHSZ];   // K pre-scaled by log2(e)
__device__ __half        g_vf[BHSZ];
__device__ __half        g_ctx[MT * DM];

// ---------------- helpers ----------------
__device__ __forceinline__ uint32_t smem_u32(const void* p) {
    uint32_t a;
    asm("{ .reg .u64 t; cvta.to.shared.u64 t, %1; cvt.u32.u64 %0, t; }" : "=r"(a) : "l"(p));
    return a;
}
__device__ __forceinline__ float ex2f(float x) {
    float y;
    asm("ex2.approx.f32 %0, %1;" : "=f"(y) : "f"(x));
    return y;
}
__device__ __forceinline__ void cp16(uint32_t dst, const void* src) {
    asm volatile("cp.async.cg.shared.global [%0], [%1], 16;" :: "r"(dst), "l"(src));
}
__device__ __forceinline__ void cp_commit() { asm volatile("cp.async.commit_group;" ::: "memory"); }
template<int N> __device__ __forceinline__ void cp_wait() {
    asm volatile("cp.async.wait_group %0;" :: "n"(N) : "memory");
}
__device__ __forceinline__ void ldm_x4(uint32_t a, uint32_t& r0, uint32_t& r1,
                                       uint32_t& r2, uint32_t& r3) {
    asm volatile("ldmatrix.sync.aligned.m8n8.x4.shared.b16 {%0,%1,%2,%3}, [%4];"
                 : "=r"(r0), "=r"(r1), "=r"(r2), "=r"(r3) : "r"(a));
}
__device__ __forceinline__ void ldm_x4t(uint32_t a, uint32_t& r0, uint32_t& r1,
                                        uint32_t& r2, uint32_t& r3) {
    asm volatile("ldmatrix.sync.aligned.m8n8.x4.trans.shared.b16 {%0,%1,%2,%3}, [%4];"
                 : "=r"(r0), "=r"(r1), "=r"(r2), "=r"(r3) : "r"(a));
}
__device__ __forceinline__ void mma16816(float* c, const uint32_t* a, const uint32_t* b) {
    asm volatile("mma.sync.aligned.m16n8k16.row.col.f32.bf16.bf16.f32 "
                 "{%0,%1,%2,%3},{%4,%5,%6,%7},{%8,%9},{%0,%1,%2,%3};"
                 : "+f"(c[0]), "+f"(c[1]), "+f"(c[2]), "+f"(c[3])
                 : "r"(a[0]), "r"(a[1]), "r"(a[2]), "r"(a[3]), "r"(b[0]), "r"(b[1]));
}
__device__ __forceinline__ void mma16816h(float* c, const uint32_t* a, const uint32_t* b) {
    asm volatile("mma.sync.aligned.m16n8k16.row.col.f32.f16.f16.f32 "
                 "{%0,%1,%2,%3},{%4,%5,%6,%7},{%8,%9},{%0,%1,%2,%3};"
                 : "+f"(c[0]), "+f"(c[1]), "+f"(c[2]), "+f"(c[3])
                 : "r"(a[0]), "r"(a[1]), "r"(a[2]), "r"(a[3]), "r"(b[0]), "r"(b[1]));
}
__device__ __forceinline__ void pksplit(float x, float y, uint32_t& hi, uint32_t& lo) {
    __nv_bfloat162 h = __floats2bfloat162_rn(x, y);
    __nv_bfloat162 l = __floats2bfloat162_rn(x - __bfloat162float(h.x),
                                             y - __bfloat162float(h.y));
    hi = *(uint32_t*)&h; lo = *(uint32_t*)&l;
}

// ---------------- fused prep ----------------
#define SPLIT_BLOCKS (MT * DM / 1024)
#define PREP_BLOCKS  (SPLIT_BLOCKS + 4096)

__global__ void prep_all(const float4* __restrict__ in,
                         __nv_bfloat16* __restrict__ hi, __nv_bfloat16* __restrict__ lo,
                         __half* __restrict__ hf,
                         const float* __restrict__ w0, const float* __restrict__ w1,
                         const float* __restrict__ w2, const float* __restrict__ w3,
                         __nv_bfloat16* __restrict__ ohi, __nv_bfloat16* __restrict__ olo,
                         __half* __restrict__ wvh, __half* __restrict__ wvl,
                         __half* __restrict__ wof)
{
    __shared__ float t[32][33];
    const int tid = threadIdx.x;
    if (blockIdx.x < SPLIT_BLOCKS) {
        int i = blockIdx.x * 256 + tid;
        float4 v = in[i];
        float f[4] = {v.x, v.y, v.z, v.w};
        __nv_bfloat16 h4[4], l4[4];
        __half f4[4];
#pragma unroll
        for (int j = 0; j < 4; ++j) {
            h4[j] = __float2bfloat16(f[j]);
            l4[j] = __float2bfloat16(f[j] - __bfloat162float(h4[j]));
            f4[j] = __float2half_rn(f[j]);
        }
        *(uint2*)(hi + (size_t)i * 4) = *(uint2*)h4;
        *(uint2*)(lo + (size_t)i * 4) = *(uint2*)l4;
        *(uint2*)(hf + (size_t)i * 4) = *(uint2*)f4;
        return;
    }
    int tb = blockIdx.x - SPLIT_BLOCKS;
    int z  = tb >> 10;
    int bx = tb & 31, by = (tb >> 5) & 31;
    int tx = tid & 31, ty = tid >> 5;
    const float* w = z == 0 ? w0 : z == 1 ? w1 : z == 2 ? w2 : w3;
    int x0 = bx * 32, y0 = by * 32;
    for (int i = ty; i < 32; i += 8)
        t[i][tx] = w[(size_t)(y0 + i) * DM + x0 + tx];
    __syncthreads();
    if (z < 2) {
        size_t zoff = (size_t)z * DM * DM;
        for (int i = ty; i < 32; i += 8) {
            float v = t[tx][i];
            __nv_bfloat16 hb = __float2bfloat16(v);
            __nv_bfloat16 lb = __float2bfloat16(v - __bfloat162float(hb));
            size_t o = zoff + (size_t)(x0 + i) * DM + y0 + tx;
            ohi[o] = hb; olo[o] = lb;
        }
    } else if (z == 2) {
        for (int i = ty; i < 32; i += 8) {
            float v = t[tx][i];
            __half hh = __float2half_rn(v);
            __half hl = __float2half_rn(v - __half2float(hh));
            size_t o = (size_t)(x0 + i) * DM + y0 + tx;
            wvh[o] = hh; wvl[o] = hl;
        }
    } else {
        for (int i = ty; i < 32; i += 8) {
            size_t o = (size_t)(x0 + i) * DM + y0 + tx;
            wof[o] = __float2half_rn(t[tx][i]);
        }
    }
}

// ---------------- fused QKV GEMM: KCH=16, 4-stage, occ 2, x4 B-pairs ----------------
#define KC2   16
#define NK2   (DM / KC2)
#define RW2   48
#define T2    (128 * 48)
#define QST2  (4 * T2)
#define QKV_SMEM (4 * QST2)

__global__ __launch_bounds__(256, 2) void gemm_qkv(
    const __nv_bfloat16* __restrict__ Ah, const __nv_bfloat16* __restrict__ Al,
    const __half* __restrict__ Af,
    const __nv_bfloat16* __restrict__ Wqk_h, const __nv_bfloat16* __restrict__ Wqk_l,
    const __half* __restrict__ Wv_h, const __half* __restrict__ Wv_l,
    __nv_bfloat16* __restrict__ qh, __nv_bfloat16* __restrict__ ql,
    __nv_bfloat16* __restrict__ kh, __nv_bfloat16* __restrict__ kl,
    __half* __restrict__ vf)
{
    extern __shared__ __align__(16) char dsm[];
    const uint32_t base = smem_u32(dsm);
    const int tid = threadIdx.x, lane = tid & 31, wid = tid >> 5;
    const int warpM = wid & 1, warpN = wid >> 1;
    const int m0 = blockIdx.y * 128, n0 = blockIdx.x * 128;
    const int which = n0 >> 10;
    const bool isV = (which == 2);

    const int lrow = tid >> 1;
    const int lu   = tid & 1;

    const __nv_bfloat16* Ahp = Ah + (size_t)m0 * DM;
    const __nv_bfloat16* Alp = Al + (size_t)m0 * DM;
    const __half*        Afp = Af + (size_t)m0 * DM;
    const __nv_bfloat16* Bhp = Wqk_h + (size_t)n0 * DM;
    const __nv_bfloat16* Blp = Wqk_l + (size_t)n0 * DM;
    const __half*        Vhp = Wv_h + (size_t)(n0 - 2048) * DM;
    const __half*        Vlp = Wv_l + (size_t)(n0 - 2048) * DM;

    auto issue = [&](int kc, int st) {
        uint32_t sb = base + st * QST2;
        uint32_t d  = sb + lrow * RW2 + lu * 16;
        size_t   go = (size_t)lrow * DM + kc + lu * 8;
        if (isV) {
            cp16(d,          Afp + go);
            cp16(d + 2 * T2, Vhp + go);
            cp16(d + 3 * T2, Vlp + go);
        } else {
            cp16(d,          Ahp + go);
            cp16(d + T2,     Alp + go);
            cp16(d + 2 * T2, Bhp + go);
            cp16(d + 3 * T2, Blp + go);
        }
        cp_commit();
    };

    float acc[4][4][4];
#pragma unroll
    for (int i = 0; i < 4; ++i)
#pragma unroll
        for (int j = 0; j < 4; ++j)
#pragma unroll
            for (int r = 0; r < 4; ++r) acc[i][j][r] = 0.f;

    issue(0, 0); issue(KC2, 1); issue(2 * KC2, 2);

    const uint32_t aRow  = (uint32_t)(warpM * 64 + (lane & 15));
    const uint32_t aCol  = (uint32_t)(((lane >> 4) & 1) * 16);
    const uint32_t bRowX = (uint32_t)(warpN * 32 + ((lane >> 4) & 1) * 8 + (lane & 7));
    const uint32_t bColX = (uint32_t)(((lane >> 3) & 1) * 16);

    if (isV) {
        for (int kt = 0; kt < NK2; ++kt) {
            cp_wait<2>();
            __syncthreads();
            if (kt + 3 < NK2) issue((kt + 3) * KC2, (kt + 3) & 3);
            else cp_commit();

            uint32_t sb = base + (kt & 3) * QST2;
            uint32_t bh[4][2], bl[4][2];
#pragma unroll
            for (int jp = 0; jp < 2; ++jp) {
                uint32_t b = sb + 2 * T2 + (bRowX + jp * 16) * RW2 + bColX;
                ldm_x4(b,      bh[2*jp][0], bh[2*jp][1], bh[2*jp+1][0], bh[2*jp+1][1]);
                ldm_x4(b + T2, bl[2*jp][0], bl[2*jp][1], bl[2*jp+1][0], bl[2*jp+1][1]);
            }
#pragma unroll
            for (int i = 0; i < 4; ++i) {
                uint32_t a = sb + (aRow + i * 16) * RW2 + aCol;
                uint32_t af[4];
                ldm_x4(a, af[0], af[1], af[2], af[3]);
#pragma unroll
                for (int j = 0; j < 4; ++j) {
                    mma16816h(acc[i][j], af, bh[j]);
                    mma16816h(acc[i][j], af, bl[j]);
                }
            }
        }
    } else {
        for (int kt = 0; kt < NK2; ++kt) {
            cp_wait<2>();
            __syncthreads();
            if (kt + 3 < NK2) issue((kt + 3) * KC2, (kt + 3) & 3);
            else cp_commit();

            uint32_t sb = base + (kt & 3) * QST2;
            uint32_t bh[4][2], bl[4][2];
#pragma unroll
            for (int jp = 0; jp < 2; ++jp) {
                uint32_t b = sb + 2 * T2 + (bRowX + jp * 16) * RW2 + bColX;
                ldm_x4(b,      bh[2*jp][0], bh[2*jp][1], bh[2*jp+1][0], bh[2*jp+1][1]);
                ldm_x4(b + T2, bl[2*jp][0], bl[2*jp][1], bl[2*jp+1][0], bl[2*jp+1][1]);
            }
#pragma unroll
            for (int i = 0; i < 4; ++i) {
                uint32_t a = sb + (aRow + i * 16) * RW2 + aCol;
                uint32_t ah[4], al[4];
                ldm_x4(a,      ah[0], ah[1], ah[2], ah[3]);
                ldm_x4(a + T2, al[0], al[1], al[2], al[3]);
#pragma unroll
                for (int j = 0; j < 4; ++j) {
                    mma16816(acc[i][j], ah, bh[j]);
                    mma16816(acc[i][j], ah, bl[j]);
                    mma16816(acc[i][j], al, bh[j]);
                }
            }
        }
    }

    __nv_bfloat16* oH = (which == 0) ? qh : kh;
    __nv_bfloat16* oL = (which == 0) ? ql : kl;
    const float sc = (which == 1) ? LOG2E : 1.f;

#pragma unroll
    for (int i = 0; i < 4; ++i) {
        int mA = m0 + warpM * 64 + i * 16 + (lane >> 2);
        int mB = mA + 8;
#pragma unroll
        for (int j = 0; j < 4; ++j) {
            int n = n0 + warpN * 32 + j * 8 + ((lane & 3) << 1);
            int nn = n & 1023;
            int hh = nn >> 6, dd = nn & 63;
            int bA = mA >> 11, sA = mA & (S_LEN - 1);
            int bB = mB >> 11, sB = mB & (S_LEN - 1);
            size_t oA = ((size_t)(bA * NH + hh) * S_LEN + sA) * DK + dd;
            size_t oB = ((size_t)(bB * NH + hh) * S_LEN + sB) * DK + dd;
            if (isV) {
                __half2 v0 = __floats2half2_rn(acc[i][j][0], acc[i][j][1]);
                __half2 v1 = __floats2half2_rn(acc[i][j][2], acc[i][j][3]);
                *(uint32_t*)(vf + oA) = *(uint32_t*)&v0;
                *(uint32_t*)(vf + oB) = *(uint32_t*)&v1;
            } else {
                uint32_t h0, l0, h1, l1;
                pksplit(acc[i][j][0] * sc, acc[i][j][1] * sc, h0, l0);
                pksplit(acc[i][j][2] * sc, acc[i][j][3] * sc, h1, l1);
                *(uint32_t*)(oH + oA) = h0; *(uint32_t*)(oL + oA) = l0;
                *(uint32_t*)(oH + oB) = h1; *(uint32_t*)(oL + oB) = l1;
            }
        }
    }
}

// ---------------- out-projection GEMM: KCH=64, 144B rows, 3-stage, occ 2 ----------------
#define KC4   64
#define NK4   (DM / KC4)               // 16
#define RW4   144                      // 128 B data + 16 B pad (stride 9 granules)
#define T4    (128 * 144)              // 18432 bytes per tile
#define OST5  (2 * T4)                 // 36864 per stage (A + B)
#define OUT_SMEM (3 * OST5)            // 110592

__global__ __launch_bounds__(256, 2) void gemm_out(
    const __half* __restrict__ Af, const __half* __restrict__ Bf,
    float* __restrict__ outF)
{
    extern __shared__ __align__(16) char dsm[];
    const uint32_t base = smem_u32(dsm);
    const int tid = threadIdx.x, lane = tid & 31, wid = tid >> 5;
    const int warpM = wid & 1, warpN = wid >> 1;
    const int m0 = blockIdx.y * 128, n0 = blockIdx.x * 128;

    const __half* Ap = Af + (size_t)m0 * DM;
    const __half* Bp = Bf + (size_t)n0 * DM;

    const int lrow = tid >> 3;          // 0..31 (4 row-iters -> 128)
    const int lu   = tid & 7;           // 16B unit within 128B row

    auto issue = [&](int kc, int st) {
        uint32_t sb = base + st * OST5;
#pragma unroll
        for (int t = 0; t < 4; ++t) {
            int row = lrow + t * 32;
            uint32_t d = sb + row * RW4 + lu * 16;
            size_t  go = (size_t)row * DM + kc + lu * 8;
            cp16(d,      Ap + go);
            cp16(d + T4, Bp + go);
        }
        cp_commit();
    };

    float acc[4][4][4];
#pragma unroll
    for (int i = 0; i < 4; ++i)
#pragma unroll
        for (int j = 0; j < 4; ++j)
#pragma unroll
            for (int r = 0; r < 4; ++r) acc[i][j][r] = 0.f;

    issue(0, 0); issue(KC4, 1);

    const uint32_t aRow  = (uint32_t)(warpM * 64 + (lane & 15));
    const uint32_t aCol  = (uint32_t)(((lane >> 4) & 1) * 16);
    const uint32_t bRowX = (uint32_t)(warpN * 32 + ((lane >> 4) & 1) * 8 + (lane & 7));
    const uint32_t bColX = (uint32_t)(((lane >> 3) & 1) * 16);

    for (int kt = 0; kt < NK4; ++kt) {
        cp_wait<1>();
        __syncthreads();
        if (kt + 2 < NK4) issue((kt + 2) * KC4, (kt + 2) % 3);
        else cp_commit();

        uint32_t sb = base + (kt % 3) * OST5;
#pragma unroll
        for (int s = 0; s < 4; ++s) {    // four k16 steps per stage
            uint32_t bf[4][2];
#pragma unroll
            for (int jp = 0; jp < 2; ++jp) {
                uint32_t b = sb + T4 + (bRowX + jp * 16) * RW4 + s * 32 + bColX;
                ldm_x4(b, bf[2*jp][0], bf[2*jp][1], bf[2*jp+1][0], bf[2*jp+1][1]);
            }
#pragma unroll
            for (int i = 0; i < 4; ++i) {
                uint32_t a = sb + (aRow + i * 16) * RW4 + s * 32 + aCol;
                uint32_t af[4];
                ldm_x4(a, af[0], af[1], af[2], af[3]);
#pragma unroll
                for (int j = 0; j < 4; ++j)
                    mma16816h(acc[i][j], af, bf[j]);
            }
        }
    }

#pragma unroll
    for (int i = 0; i < 4; ++i) {
        int mA = m0 + warpM * 64 + i * 16 + (lane >> 2);
        int mB = mA + 8;
#pragma unroll
        for (int j = 0; j < 4; ++j) {
            int n = n0 + warpN * 32 + j * 8 + ((lane & 3) << 1);
            *(float2*)(outF + (size_t)mA * DM + n) = make_float2(acc[i][j][0], acc[i][j][1]);
            *(float2*)(outF + (size_t)mB * DM + n) = make_float2(acc[i][j][2], acc[i][j][3]);
        }
    }
}

// ---------------- HMMA flash attention (unchanged) ----------------
__device__ __forceinline__ int t5_bucket(int delta)
{
    int base = (delta > 0) ? 16 : 0;
    int a = delta < 0 ? -delta : delta;
    int bucket;
    if (a < 8) bucket = a;
    else if (a >= 128) bucket = 15;
    else {
        int t = 31 - __clz(a);
        int f = (a * a >= (1 << (2 * t + 1))) ? 1 : 0;
        bucket = 2 + 2 * t + f;
        if (bucket > 15) bucket = 15;
    }
    return base + bucket;
}

#define PQ        144
#define A_QH      0
#define A_QL      18432
#define A_BUF     36864
#define A_BUFSZ   27648
#define A_KH      0
#define A_KL      9216
#define A_V       18432
#define A_BIAS    (A_BUF + 2*A_BUFSZ)
#define BIAS_N    4096
#define ATT_SMEM  (A_BIAS + BIAS_N*4)

__global__ __launch_bounds__(256, 2) void attn_mma(
    const __nv_bfloat16* __restrict__ qh, const __nv_bfloat16* __restrict__ ql,
    const __nv_bfloat16* __restrict__ kh, const __nv_bfloat16* __restrict__ kl,
    const __half* __restrict__ vf, const float* __restrict__ rel_bias,
    __half* __restrict__ cf)
{
    extern __shared__ __align__(16) char asmem[];
    const uint32_t base = smem_u32(asmem);
    float* bias = (float*)(asmem + A_BIAS);

    const int tid = threadIdx.x, lane = tid & 31, wid = tid >> 5;
    const int bh = blockIdx.y;
    const int hd = bh & (NH - 1);
    const int b  = bh >> 4;
    const int q0 = blockIdx.x * 128;
    const size_t bo = (size_t)bh * S_LEN * DK;

    for (int i = tid; i < BIAS_N; i += 256)
        bias[i] = rel_bias[t5_bucket(i - 2047) * NH + hd] * LOG2E;

#pragma unroll
    for (int it = 0; it < 8; ++it) {
        int idx = tid + it * 256;
        int sub = idx & 1023, row = sub >> 3, u = sub & 7;
        const __nv_bfloat16* src = (it < 4) ? qh : ql;
        cp16(base + (it < 4 ? A_QH : A_QL) + row * PQ + u * 16,
             src + bo + (size_t)(q0 + row) * DK + u * 8);
    }
    auto issue_kv = [&](int t, int buf) {
        uint32_t bb = base + A_BUF + buf * A_BUFSZ;
#pragma unroll
        for (int it = 0; it < 6; ++it) {
            int idx = tid + it * 256;
            int sub = idx & 511, row = sub >> 3, u = sub & 7;
            if (it < 4) {
                const __nv_bfloat16* src = (it < 2) ? kh : kl;
                uint32_t toff = (it < 2) ? A_KH : A_KL;
                cp16(bb + toff + row * PQ + u * 16,
                     src + bo + (size_t)(t * 64 + row) * DK + u * 8);
            } else {
                cp16(bb + A_V + row * PQ + u * 16,
                     vf + bo + (size_t)(t * 64 + row) * DK + u * 8);
            }
        }
        cp_commit();
    };
    issue_kv(0, 0);
    issue_kv(1, 1);

    const int g  = lane >> 2;
    const int tc = lane & 3;
    const int qg0 = q0 + wid * 16 + g;
    const int qg1 = qg0 + 8;

    float acc_o[8][4];
#pragma unroll
    for (int j = 0; j < 8; ++j)
#pragma unroll
        for (int r = 0; r < 4; ++r) acc_o[j][r] = 0.f;
    float m0 = -1e30f, m1 = -1e30f, l0 = 0.f, l1 = 0.f;

    const uint32_t aBase = base + (wid * 16 + (lane & 15)) * PQ + ((lane >> 4) & 1) * 16;
    const uint32_t bRowSel = ((lane >> 4) & 1) * 8 + (lane & 7);
    const uint32_t bColSel = ((lane >> 3) & 1) * 16;
    const uint32_t vRowSel = ((lane >> 3) & 1) * 8 + (lane & 7);
    const uint32_t vColSel = ((lane >> 4) & 1) * 16;

    for (int t = 0; t < 32; ++t) {
        if (t + 2 < 32) cp_wait<1>(); else cp_wait<0>();
        __syncthreads();
        uint32_t kb = base + A_BUF + (t & 1) * A_BUFSZ;

        float s[8][4];
#pragma unroll
        for (int j = 0; j < 8; ++j)
#pragma unroll
            for (int r = 0; r < 4; ++r) s[j][r] = 0.f;

#pragma unroll
        for (int ks = 0; ks < 4; ++ks) {
            uint32_t ah[4], al[4];
            ldm_x4(aBase + ks * 32,        ah[0], ah[1], ah[2], ah[3]);
            ldm_x4(aBase + A_QL + ks * 32, al[0], al[1], al[2], al[3]);
#pragma unroll
            for (int nb2 = 0; nb2 < 4; ++nb2) {
                uint32_t bAddr = kb + A_KH + (nb2 * 16 + bRowSel) * PQ + bColSel + ks * 32;
                uint32_t h0, h1, h2, h3, u0, u1, u2, u3;
                ldm_x4(bAddr,                 h0, h1, h2, h3);
                ldm_x4(bAddr + (A_KL - A_KH), u0, u1, u2, u3);
                uint32_t bh0[2] = {h0, h1}, bh1[2] = {h2, h3};
                uint32_t bl0[2] = {u0, u1}, bl1[2] = {u2, u3};
                mma16816(s[2*nb2],   ah, bh0); mma16816(s[2*nb2],   ah, bl0);
                mma16816(s[2*nb2],   al, bh0);
                mma16816(s[2*nb2+1], ah, bh1); mma16816(s[2*nb2+1], ah, bl1);
                mma16816(s[2*nb2+1], al, bh1);
            }
        }

        int ktb = t * 64;
        float rm0 = -1e30f, rm1 = -1e30f;
        int i0base = ktb + tc * 2 - qg0 + 2047;
        int i1base = ktb + tc * 2 - qg1 + 2047;
#pragma unroll
        for (int nb = 0; nb < 8; ++nb) {
            int i00 = i0base + nb * 8;
            int i10 = i1base + nb * 8;
            s[nb][0] += bias[i00]; s[nb][1] += bias[i00 + 1];
            s[nb][2] += bias[i10]; s[nb][3] += bias[i10 + 1];
            rm0 = fmaxf(rm0, fmaxf(s[nb][0], s[nb][1]));
            rm1 = fmaxf(rm1, fmaxf(s[nb][2], s[nb][3]));
        }
        rm0 = fmaxf(rm0, __shfl_xor_sync(0xffffffffu, rm0, 1));
        rm0 = fmaxf(rm0, __shfl_xor_sync(0xffffffffu, rm0, 2));
        rm1 = fmaxf(rm1, __shfl_xor_sync(0xffffffffu, rm1, 1));
        rm1 = fmaxf(rm1, __shfl_xor_sync(0xffffffffu, rm1, 2));

        bool upd = __any_sync(0xffffffffu, (rm0 > m0) | (rm1 > m1));
        if (upd) {
            float mn0 = fmaxf(m0, rm0), mn1 = fmaxf(m1, rm1);
            float c0 = ex2f(m0 - mn0), c1 = ex2f(m1 - mn1);
            m0 = mn0; m1 = mn1;
            l0 *= c0; l1 *= c1;
#pragma unroll
            for (int j = 0; j < 8; ++j) {
                acc_o[j][0] *= c0; acc_o[j][1] *= c0;
                acc_o[j][2] *= c1; acc_o[j][3] *= c1;
            }
        }

        float ps0 = 0.f, ps1 = 0.f;
#pragma unroll
        for (int nb = 0; nb < 8; ++nb) {
            s[nb][0] = ex2f(s[nb][0] - m0); s[nb][1] = ex2f(s[nb][1] - m0);
            s[nb][2] = ex2f(s[nb][2] - m1); s[nb][3] = ex2f(s[nb][3] - m1);
            ps0 += s[nb][0] + s[nb][1];
            ps1 += s[nb][2] + s[nb][3];
        }
        ps0 += __shfl_xor_sync(0xffffffffu, ps0, 1);
        ps0 += __shfl_xor_sync(0xffffffffu, ps0, 2);
        ps1 += __shfl_xor_sync(0xffffffffu, ps1, 1);
        ps1 += __shfl_xor_sync(0xffffffffu, ps1, 2);
        l0 += ps0; l1 += ps1;

#pragma unroll
        for (int ks = 0; ks < 4; ++ks) {
            uint32_t ap[4];
            __half2 p0 = __floats2half2_rn(s[2*ks][0],   s[2*ks][1]);
            __half2 p1 = __floats2half2_rn(s[2*ks][2],   s[2*ks][3]);
            __half2 p2 = __floats2half2_rn(s[2*ks+1][0], s[2*ks+1][1]);
            __half2 p3 = __floats2half2_rn(s[2*ks+1][2], s[2*ks+1][3]);
            ap[0] = *(uint32_t*)&p0; ap[1] = *(uint32_t*)&p1;
            ap[2] = *(uint32_t*)&p2; ap[3] = *(uint32_t*)&p3;
#pragma unroll
            for (int db2 = 0; db2 < 4; ++db2) {
                uint32_t vAddr = kb + A_V + (ks * 16 + vRowSel) * PQ + db2 * 32 + vColSel;
                uint32_t h0, h1, h2, h3;
                ldm_x4t(vAddr, h0, h1, h2, h3);
                uint32_t v0[2] = {h0, h1}, v1[2] = {h2, h3};
                mma16816h(acc_o[2*db2],   ap, v0);
                mma16816h(acc_o[2*db2+1], ap, v1);
            }
        }
        __syncthreads();
        if (t + 2 < 32) issue_kv(t + 2, t & 1);
    }

    float inv0 = 1.f / l0, inv1 = 1.f / l1;
#pragma unroll
    for (int db = 0; db < 8; ++db) {
        int dcol = hd * DK + db * 8 + tc * 2;
        size_t o0 = ((size_t)b * S_LEN + qg0) * DM + dcol;
        size_t o1 = ((size_t)b * S_LEN + qg1) * DM + dcol;
        __half2 w0 = __floats2half2_rn(acc_o[db][0] * inv0, acc_o[db][1] * inv0);
        __half2 w1 = __floats2half2_rn(acc_o[db][2] * inv1, acc_o[db][3] * inv1);
        *(uint32_t*)(cf + o0) = *(uint32_t*)&w0;
        *(uint32_t*)(cf + o1) = *(uint32_t*)&w1;
    }
}

// ---------------------------------------------------------------------------
extern "C" void kernel_launch(void* const* d_in, const int* in_sizes, int n_in,
                              void* d_out, int out_size)
{
    const float* hidden  = (const float*)d_in[0];
    const float* wq      = (const float*)d_in[1];
    const float* wk      = (const float*)d_in[2];
    const float* wv      = (const float*)d_in[3];
    const float* wo      = (const float*)d_in[4];
    const float* relbias = (const float*)d_in[5];
    float* out = (float*)d_out;

    __nv_bfloat16 *hhi, *hlo, *whi, *wlo, *qh, *ql, *kh, *kl;
    __half *hf, *wvh, *wvl, *wof, *vf, *cf;
    cudaGetSymbolAddress((void**)&hhi, g_h_hi);
    cudaGetSymbolAddress((void**)&hlo, g_h_lo);
    cudaGetSymbolAddress((void**)&hf,  g_h_f);
    cudaGetSymbolAddress((void**)&whi, g_wt_hi);
    cudaGetSymbolAddress((void**)&wlo, g_wt_lo);
    cudaGetSymbolAddress((void**)&wvh, g_wv_hi);
    cudaGetSymbolAddress((void**)&wvl, g_wv_lo);
    cudaGetSymbolAddress((void**)&wof, g_wo_f);
    cudaGetSymbolAddress((void**)&qh,  g_qh);
    cudaGetSymbolAddress((void**)&ql,  g_ql);
    cudaGetSymbolAddress((void**)&kh,  g_kh);
    cudaGetSymbolAddress((void**)&kl,  g_kl);
    cudaGetSymbolAddress((void**)&vf,  g_vf);
    cudaGetSymbolAddress((void**)&cf,  g_ctx);

    cudaFuncSetAttribute(gemm_qkv, cudaFuncAttributeMaxDynamicSharedMemorySize, QKV_SMEM);
    cudaFuncSetAttribute(gemm_out, cudaFuncAttributeMaxDynamicSharedMemorySize, OUT_SMEM);
    cudaFuncSetAttribute(attn_mma, cudaFuncAttributeMaxDynamicSharedMemorySize, ATT_SMEM);

    prep_all<<<PREP_BLOCKS, 256>>>((const float4*)hidden, hhi, hlo, hf,
                                   wq, wk, wv, wo, whi, wlo, wvh, wvl, wof);

    gemm_qkv<<<dim3(24, 64), 256, QKV_SMEM>>>(hhi, hlo, hf, whi, wlo, wvh, wvl,
                                              qh, ql, kh, kl, vf);

    attn_mma<<<dim3(16, 64), 256, ATT_SMEM>>>(qh, ql, kh, kl, vf, relbias, cf);

    gemm_out<<<dim3(8, 64), 256, OUT_SMEM>>>(cf, wof, out);
}

// round 17
// speedup vs baseline: 1.0221x; 1.0221x over previous
#include <cuda_runtime.h>
#include <cuda_bf16.h>
#include <cuda_fp16.h>
#include <cstdint>

#define BATCH 4
#define S_LEN 2048
#define NH    16
#define DK    64
#define DM    1024
#define MT    (BATCH*S_LEN)
#define BHSZ  ((size_t)BATCH * NH * S_LEN * DK)
#define LOG2E 1.4426950408889634f

__device__ __nv_bfloat16 g_h_hi[MT * DM];
__device__ __nv_bfloat16 g_h_lo[MT * DM];
__device__ __half        g_h_f[MT * DM];
__device__ __nv_bfloat16 g_wt_hi[2 * DM * DM];
__device__ __nv_bfloat16 g_wt_lo[2 * DM * DM];
__device__ __half        g_wv_hi[DM * DM];
__device__ __half        g_wv_lo[DM * DM];
__device__ __half        g_wo_f[DM * DM];
__device__ __nv_bfloat16 g_qh[BHSZ], g_ql[BHSZ];
__device__ __nv_bfloat16 g_kh[BHSZ], g_kl[BHSZ];   // K pre-scaled by log2(e)
__device__ __half        g_vf[BHSZ];
__device__ __half        g_ctx[MT * DM];

// ---------------- helpers ----------------
__device__ __forceinline__ uint32_t smem_u32(const void* p) {
    uint32_t a;
    asm("{ .reg .u64 t; cvta.to.shared.u64 t, %1; cvt.u32.u64 %0, t; }" : "=r"(a) : "l"(p));
    return a;
}
__device__ __forceinline__ float ex2f(float x) {
    float y;
    asm("ex2.approx.f32 %0, %1;" : "=f"(y) : "f"(x));
    return y;
}
__device__ __forceinline__ void cp16(uint32_t dst, const void* src) {
    asm volatile("cp.async.cg.shared.global [%0], [%1], 16;" :: "r"(dst), "l"(src));
}
__device__ __forceinline__ void cp_commit() { asm volatile("cp.async.commit_group;" ::: "memory"); }
template<int N> __device__ __forceinline__ void cp_wait() {
    asm volatile("cp.async.wait_group %0;" :: "n"(N) : "memory");
}
__device__ __forceinline__ void ldm_x4(uint32_t a, uint32_t& r0, uint32_t& r1,
                                       uint32_t& r2, uint32_t& r3) {
    asm volatile("ldmatrix.sync.aligned.m8n8.x4.shared.b16 {%0,%1,%2,%3}, [%4];"
                 : "=r"(r0), "=r"(r1), "=r"(r2), "=r"(r3) : "r"(a));
}
__device__ __forceinline__ void ldm_x4t(uint32_t a, uint32_t& r0, uint32_t& r1,
                                        uint32_t& r2, uint32_t& r3) {
    asm volatile("ldmatrix.sync.aligned.m8n8.x4.trans.shared.b16 {%0,%1,%2,%3}, [%4];"
                 : "=r"(r0), "=r"(r1), "=r"(r2), "=r"(r3) : "r"(a));
}
__device__ __forceinline__ void mma16816(float* c, const uint32_t* a, const uint32_t* b) {
    asm volatile("mma.sync.aligned.m16n8k16.row.col.f32.bf16.bf16.f32 "
                 "{%0,%1,%2,%3},{%4,%5,%6,%7},{%8,%9},{%0,%1,%2,%3};"
                 : "+f"(c[0]), "+f"(c[1]), "+f"(c[2]), "+f"(c[3])
                 : "r"(a[0]), "r"(a[1]), "r"(a[2]), "r"(a[3]), "r"(b[0]), "r"(b[1]));
}
__device__ __forceinline__ void mma16816h(float* c, const uint32_t* a, const uint32_t* b) {
    asm volatile("mma.sync.aligned.m16n8k16.row.col.f32.f16.f16.f32 "
                 "{%0,%1,%2,%3},{%4,%5,%6,%7},{%8,%9},{%0,%1,%2,%3};"
                 : "+f"(c[0]), "+f"(c[1]), "+f"(c[2]), "+f"(c[3])
                 : "r"(a[0]), "r"(a[1]), "r"(a[2]), "r"(a[3]), "r"(b[0]), "r"(b[1]));
}
__device__ __forceinline__ void pksplit(float x, float y, uint32_t& hi, uint32_t& lo) {
    __nv_bfloat162 h = __floats2bfloat162_rn(x, y);
    __nv_bfloat162 l = __floats2bfloat162_rn(x - __bfloat162float(h.x),
                                             y - __bfloat162float(h.y));
    hi = *(uint32_t*)&h; lo = *(uint32_t*)&l;
}

// ---------------- fused prep ----------------
#define SPLIT_BLOCKS (MT * DM / 1024)
#define PREP_BLOCKS  (SPLIT_BLOCKS + 4096)

__global__ void prep_all(const float4* __restrict__ in,
                         __nv_bfloat16* __restrict__ hi, __nv_bfloat16* __restrict__ lo,
                         __half* __restrict__ hf,
                         const float* __restrict__ w0, const float* __restrict__ w1,
                         const float* __restrict__ w2, const float* __restrict__ w3,
                         __nv_bfloat16* __restrict__ ohi, __nv_bfloat16* __restrict__ olo,
                         __half* __restrict__ wvh, __half* __restrict__ wvl,
                         __half* __restrict__ wof)
{
    __shared__ float t[32][33];
    const int tid = threadIdx.x;
    if (blockIdx.x < SPLIT_BLOCKS) {
        int i = blockIdx.x * 256 + tid;
        float4 v = in[i];
        float f[4] = {v.x, v.y, v.z, v.w};
        __nv_bfloat16 h4[4], l4[4];
        __half f4[4];
#pragma unroll
        for (int j = 0; j < 4; ++j) {
            h4[j] = __float2bfloat16(f[j]);
            l4[j] = __float2bfloat16(f[j] - __bfloat162float(h4[j]));
            f4[j] = __float2half_rn(f[j]);
        }
        *(uint2*)(hi + (size_t)i * 4) = *(uint2*)h4;
        *(uint2*)(lo + (size_t)i * 4) = *(uint2*)l4;
        *(uint2*)(hf + (size_t)i * 4) = *(uint2*)f4;
        return;
    }
    int tb = blockIdx.x - SPLIT_BLOCKS;
    int z  = tb >> 10;
    int bx = tb & 31, by = (tb >> 5) & 31;
    int tx = tid & 31, ty = tid >> 5;
    const float* w = z == 0 ? w0 : z == 1 ? w1 : z == 2 ? w2 : w3;
    int x0 = bx * 32, y0 = by * 32;
    for (int i = ty; i < 32; i += 8)
        t[i][tx] = w[(size_t)(y0 + i) * DM + x0 + tx];
    __syncthreads();
    if (z < 2) {
        size_t zoff = (size_t)z * DM * DM;
        for (int i = ty; i < 32; i += 8) {
            float v = t[tx][i];
            __nv_bfloat16 hb = __float2bfloat16(v);
            __nv_bfloat16 lb = __float2bfloat16(v - __bfloat162float(hb));
            size_t o = zoff + (size_t)(x0 + i) * DM + y0 + tx;
            ohi[o] = hb; olo[o] = lb;
        }
    } else if (z == 2) {
        for (int i = ty; i < 32; i += 8) {
            float v = t[tx][i];
            __half hh = __float2half_rn(v);
            __half hl = __float2half_rn(v - __half2float(hh));
            size_t o = (size_t)(x0 + i) * DM + y0 + tx;
            wvh[o] = hh; wvl[o] = hl;
        }
    } else {
        for (int i = ty; i < 32; i += 8) {
            size_t o = (size_t)(x0 + i) * DM + y0 + tx;
            wof[o] = __float2half_rn(t[tx][i]);
        }
    }
}

// ---------------- fused QKV GEMM: KCH=16, 4-stage, occ 2, x4 B-pairs ----------------
#define KC2   16
#define NK2   (DM / KC2)
#define RW2   48
#define T2    (128 * 48)
#define QST2  (4 * T2)
#define QKV_SMEM (4 * QST2)

__global__ __launch_bounds__(256, 2) void gemm_qkv(
    const __nv_bfloat16* __restrict__ Ah, const __nv_bfloat16* __restrict__ Al,
    const __half* __restrict__ Af,
    const __nv_bfloat16* __restrict__ Wqk_h, const __nv_bfloat16* __restrict__ Wqk_l,
    const __half* __restrict__ Wv_h, const __half* __restrict__ Wv_l,
    __nv_bfloat16* __restrict__ qh, __nv_bfloat16* __restrict__ ql,
    __nv_bfloat16* __restrict__ kh, __nv_bfloat16* __restrict__ kl,
    __half* __restrict__ vf)
{
    extern __shared__ __align__(16) char dsm[];
    const uint32_t base = smem_u32(dsm);
    const int tid = threadIdx.x, lane = tid & 31, wid = tid >> 5;
    const int warpM = wid & 1, warpN = wid >> 1;
    const int m0 = blockIdx.y * 128, n0 = blockIdx.x * 128;
    const int which = n0 >> 10;
    const bool isV = (which == 2);

    const int lrow = tid >> 1;
    const int lu   = tid & 1;

    const __nv_bfloat16* Ahp = Ah + (size_t)m0 * DM;
    const __nv_bfloat16* Alp = Al + (size_t)m0 * DM;
    const __half*        Afp = Af + (size_t)m0 * DM;
    const __nv_bfloat16* Bhp = Wqk_h + (size_t)n0 * DM;
    const __nv_bfloat16* Blp = Wqk_l + (size_t)n0 * DM;
    const __half*        Vhp = Wv_h + (size_t)(n0 - 2048) * DM;
    const __half*        Vlp = Wv_l + (size_t)(n0 - 2048) * DM;

    auto issue = [&](int kc, int st) {
        uint32_t sb = base + st * QST2;
        uint32_t d  = sb + lrow * RW2 + lu * 16;
        size_t   go = (size_t)lrow * DM + kc + lu * 8;
        if (isV) {
            cp16(d,          Afp + go);
            cp16(d + 2 * T2, Vhp + go);
            cp16(d + 3 * T2, Vlp + go);
        } else {
            cp16(d,          Ahp + go);
            cp16(d + T2,     Alp + go);
            cp16(d + 2 * T2, Bhp + go);
            cp16(d + 3 * T2, Blp + go);
        }
        cp_commit();
    };

    float acc[4][4][4];
#pragma unroll
    for (int i = 0; i < 4; ++i)
#pragma unroll
        for (int j = 0; j < 4; ++j)
#pragma unroll
            for (int r = 0; r < 4; ++r) acc[i][j][r] = 0.f;

    issue(0, 0); issue(KC2, 1); issue(2 * KC2, 2);

    const uint32_t aRow  = (uint32_t)(warpM * 64 + (lane & 15));
    const uint32_t aCol  = (uint32_t)(((lane >> 4) & 1) * 16);
    const uint32_t bRowX = (uint32_t)(warpN * 32 + ((lane >> 4) & 1) * 8 + (lane & 7));
    const uint32_t bColX = (uint32_t)(((lane >> 3) & 1) * 16);

    if (isV) {
        for (int kt = 0; kt < NK2; ++kt) {
            cp_wait<2>();
            __syncthreads();
            if (kt + 3 < NK2) issue((kt + 3) * KC2, (kt + 3) & 3);
            else cp_commit();

            uint32_t sb = base + (kt & 3) * QST2;
            uint32_t bh[4][2], bl[4][2];
#pragma unroll
            for (int jp = 0; jp < 2; ++jp) {
                uint32_t b = sb + 2 * T2 + (bRowX + jp * 16) * RW2 + bColX;
                ldm_x4(b,      bh[2*jp][0], bh[2*jp][1], bh[2*jp+1][0], bh[2*jp+1][1]);
                ldm_x4(b + T2, bl[2*jp][0], bl[2*jp][1], bl[2*jp+1][0], bl[2*jp+1][1]);
            }
#pragma unroll
            for (int i = 0; i < 4; ++i) {
                uint32_t a = sb + (aRow + i * 16) * RW2 + aCol;
                uint32_t af[4];
                ldm_x4(a, af[0], af[1], af[2], af[3]);
#pragma unroll
                for (int j = 0; j < 4; ++j) {
                    mma16816h(acc[i][j], af, bh[j]);
                    mma16816h(acc[i][j], af, bl[j]);
                }
            }
        }
    } else {
        for (int kt = 0; kt < NK2; ++kt) {
            cp_wait<2>();
            __syncthreads();
            if (kt + 3 < NK2) issue((kt + 3) * KC2, (kt + 3) & 3);
            else cp_commit();

            uint32_t sb = base + (kt & 3) * QST2;
            uint32_t bh[4][2], bl[4][2];
#pragma unroll
            for (int jp = 0; jp < 2; ++jp) {
                uint32_t b = sb + 2 * T2 + (bRowX + jp * 16) * RW2 + bColX;
                ldm_x4(b,      bh[2*jp][0], bh[2*jp][1], bh[2*jp+1][0], bh[2*jp+1][1]);
                ldm_x4(b + T2, bl[2*jp][0], bl[2*jp][1], bl[2*jp+1][0], bl[2*jp+1][1]);
            }
#pragma unroll
            for (int i = 0; i < 4; ++i) {
                uint32_t a = sb + (aRow + i * 16) * RW2 + aCol;
                uint32_t ah[4], al[4];
                ldm_x4(a,      ah[0], ah[1], ah[2], ah[3]);
                ldm_x4(a + T2, al[0], al[1], al[2], al[3]);
#pragma unroll
                for (int j = 0; j < 4; ++j) {
                    mma16816(acc[i][j], ah, bh[j]);
                    mma16816(acc[i][j], ah, bl[j]);
                    mma16816(acc[i][j], al, bh[j]);
                }
            }
        }
    }

    __nv_bfloat16* oH = (which == 0) ? qh : kh;
    __nv_bfloat16* oL = (which == 0) ? ql : kl;
    const float sc = (which == 1) ? LOG2E : 1.f;

#pragma unroll
    for (int i = 0; i < 4; ++i) {
        int mA = m0 + warpM * 64 + i * 16 + (lane >> 2);
        int mB = mA + 8;
#pragma unroll
        for (int j = 0; j < 4; ++j) {
            int n = n0 + warpN * 32 + j * 8 + ((lane & 3) << 1);
            int nn = n & 1023;
            int hh = nn >> 6, dd = nn & 63;
            int bA = mA >> 11, sA = mA & (S_LEN - 1);
            int bB = mB >> 11, sB = mB & (S_LEN - 1);
            size_t oA = ((size_t)(bA * NH + hh) * S_LEN + sA) * DK + dd;
            size_t oB = ((size_t)(bB * NH + hh) * S_LEN + sB) * DK + dd;
            if (isV) {
                __half2 v0 = __floats2half2_rn(acc[i][j][0], acc[i][j][1]);
                __half2 v1 = __floats2half2_rn(acc[i][j][2], acc[i][j][3]);
                *(uint32_t*)(vf + oA) = *(uint32_t*)&v0;
                *(uint32_t*)(vf + oB) = *(uint32_t*)&v1;
            } else {
                uint32_t h0, l0, h1, l1;
                pksplit(acc[i][j][0] * sc, acc[i][j][1] * sc, h0, l0);
                pksplit(acc[i][j][2] * sc, acc[i][j][3] * sc, h1, l1);
                *(uint32_t*)(oH + oA) = h0; *(uint32_t*)(oL + oA) = l0;
                *(uint32_t*)(oH + oB) = h1; *(uint32_t*)(oL + oB) = l1;
            }
        }
    }
}

// ---------------- out-projection GEMM: KCH=32, 80B rows, 4-stage, occ 2 ----------------
#define KC3   32
#define NK3   (DM / KC3)               // 32
#define RW3   80
#define T3    (128 * 80)               // 10240 bytes per tile
#define OST4  (2 * T3)                 // 20480 per stage (A + B)
#define OUT_SMEM (4 * OST4)            // 81920

__global__ __launch_bounds__(256, 2) void gemm_out(
    const __half* __restrict__ Af, const __half* __restrict__ Bf,
    float* __restrict__ outF)
{
    extern __shared__ __align__(16) char dsm[];
    const uint32_t base = smem_u32(dsm);
    const int tid = threadIdx.x, lane = tid & 31, wid = tid >> 5;
    const int warpM = wid & 1, warpN = wid >> 1;
    const int m0 = blockIdx.y * 128, n0 = blockIdx.x * 128;

    const __half* Ap = Af + (size_t)m0 * DM;
    const __half* Bp = Bf + (size_t)n0 * DM;

    const int lrow = tid >> 2;          // 0..63 (2 row-iters -> 128)
    const int lu   = tid & 3;           // 16B unit within 64B row

    auto issue = [&](int kc, int st) {
        uint32_t sb = base + st * OST4;
#pragma unroll
        for (int t = 0; t < 2; ++t) {
            int row = lrow + t * 64;
            uint32_t d = sb + row * RW3 + lu * 16;
            size_t  go = (size_t)row * DM + kc + lu * 8;
            cp16(d,      Ap + go);
            cp16(d + T3, Bp + go);
        }
        cp_commit();
    };

    float acc[4][4][4];
#pragma unroll
    for (int i = 0; i < 4; ++i)
#pragma unroll
        for (int j = 0; j < 4; ++j)
#pragma unroll
            for (int r = 0; r < 4; ++r) acc[i][j][r] = 0.f;

    issue(0, 0); issue(KC3, 1); issue(2 * KC3, 2);

    const uint32_t aRow  = (uint32_t)(warpM * 64 + (lane & 15));
    const uint32_t aCol  = (uint32_t)(((lane >> 4) & 1) * 16);
    const uint32_t bRowX = (uint32_t)(warpN * 32 + ((lane >> 4) & 1) * 8 + (lane & 7));
    const uint32_t bColX = (uint32_t)(((lane >> 3) & 1) * 16);

    for (int kt = 0; kt < NK3; ++kt) {
        cp_wait<2>();
        __syncthreads();
        if (kt + 3 < NK3) issue((kt + 3) * KC3, (kt + 3) & 3);
        else cp_commit();

        uint32_t sb = base + (kt & 3) * OST4;
#pragma unroll
        for (int s = 0; s < 2; ++s) {    // two k16 steps per stage
            uint32_t bf[4][2];
#pragma unroll
            for (int jp = 0; jp < 2; ++jp) {
                uint32_t b = sb + T3 + (bRowX + jp * 16) * RW3 + s * 32 + bColX;
                ldm_x4(b, bf[2*jp][0], bf[2*jp][1], bf[2*jp+1][0], bf[2*jp+1][1]);
            }
#pragma unroll
            for (int i = 0; i < 4; ++i) {
                uint32_t a = sb + (aRow + i * 16) * RW3 + s * 32 + aCol;
                uint32_t af[4];
                ldm_x4(a, af[0], af[1], af[2], af[3]);
#pragma unroll
                for (int j = 0; j < 4; ++j)
                    mma16816h(acc[i][j], af, bf[j]);
            }
        }
    }

#pragma unroll
    for (int i = 0; i < 4; ++i) {
        int mA = m0 + warpM * 64 + i * 16 + (lane >> 2);
        int mB = mA + 8;
#pragma unroll
        for (int j = 0; j < 4; ++j) {
            int n = n0 + warpN * 32 + j * 8 + ((lane & 3) << 1);
            *(float2*)(outF + (size_t)mA * DM + n) = make_float2(acc[i][j][0], acc[i][j][1]);
            *(float2*)(outF + (size_t)mB * DM + n) = make_float2(acc[i][j][2], acc[i][j][3]);
        }
    }
}

// ---------------- HMMA flash attention ----------------
__device__ __forceinline__ int t5_bucket(int delta)
{
    int base = (delta > 0) ? 16 : 0;
    int a = delta < 0 ? -delta : delta;
    int bucket;
    if (a < 8) bucket = a;
    else if (a >= 128) bucket = 15;
    else {
        int t = 31 - __clz(a);
        int f = (a * a >= (1 << (2 * t + 1))) ? 1 : 0;
        bucket = 2 + 2 * t + f;
        if (bucket > 15) bucket = 15;
    }
    return base + bucket;
}

#define PQ        144
#define A_QH      0
#define A_QL      18432
#define A_BUF     36864
#define A_BUFSZ   27648
#define A_KH      0
#define A_KL      9216
#define A_V       18432
#define A_BIAS    (A_BUF + 2*A_BUFSZ)
#define BIAS_N    4096
#define ATT_SMEM  (A_BIAS + BIAS_N*4)

__global__ __launch_bounds__(256, 2) void attn_mma(
    const __nv_bfloat16* __restrict__ qh, const __nv_bfloat16* __restrict__ ql,
    const __nv_bfloat16* __restrict__ kh, const __nv_bfloat16* __restrict__ kl,
    const __half* __restrict__ vf, const float* __restrict__ rel_bias,
    __half* __restrict__ cf)
{
    extern __shared__ __align__(16) char asmem[];
    const uint32_t base = smem_u32(asmem);
    float* bias = (float*)(asmem + A_BIAS);

    const int tid = threadIdx.x, lane = tid & 31, wid = tid >> 5;
    const int bh = blockIdx.y;
    const int hd = bh & (NH - 1);
    const int b  = bh >> 4;
    const int q0 = blockIdx.x * 128;
    const size_t bo = (size_t)bh * S_LEN * DK;

    for (int i = tid; i < BIAS_N; i += 256)
        bias[i] = rel_bias[t5_bucket(i - 2047) * NH + hd] * LOG2E;

#pragma unroll
    for (int it = 0; it < 8; ++it) {
        int idx = tid + it * 256;
        int sub = idx & 1023, row = sub >> 3, u = sub & 7;
        const __nv_bfloat16* src = (it < 4) ? qh : ql;
        cp16(base + (it < 4 ? A_QH : A_QL) + row * PQ + u * 16,
             src + bo + (size_t)(q0 + row) * DK + u * 8);
    }
    auto issue_kv = [&](int t, int buf) {
        uint32_t bb = base + A_BUF + buf * A_BUFSZ;
#pragma unroll
        for (int it = 0; it < 6; ++it) {
            int idx = tid + it * 256;
            int sub = idx & 511, row = sub >> 3, u = sub & 7;
            if (it < 4) {
                const __nv_bfloat16* src = (it < 2) ? kh : kl;
                uint32_t toff = (it < 2) ? A_KH : A_KL;
                cp16(bb + toff + row * PQ + u * 16,
                     src + bo + (size_t)(t * 64 + row) * DK + u * 8);
            } else {
                cp16(bb + A_V + row * PQ + u * 16,
                     vf + bo + (size_t)(t * 64 + row) * DK + u * 8);
            }
        }
        cp_commit();
    };
    issue_kv(0, 0);
    issue_kv(1, 1);

    const int g  = lane >> 2;
    const int tc = lane & 3;
    const int qg0 = q0 + wid * 16 + g;
    const int qg1 = qg0 + 8;

    float acc_o[8][4];
#pragma unroll
    for (int j = 0; j < 8; ++j)
#pragma unroll
        for (int r = 0; r < 4; ++r) acc_o[j][r] = 0.f;
    float m0 = -1e30f, m1 = -1e30f, l0 = 0.f, l1 = 0.f;

    const uint32_t aBase = base + (wid * 16 + (lane & 15)) * PQ + ((lane >> 4) & 1) * 16;
    const uint32_t bRowSel = ((lane >> 4) & 1) * 8 + (lane & 7);
    const uint32_t bColSel = ((lane >> 3) & 1) * 16;
    const uint32_t vRowSel = ((lane >> 3) & 1) * 8 + (lane & 7);
    const uint32_t vColSel = ((lane >> 4) & 1) * 16;

    for (int t = 0; t < 32; ++t) {
        if (t + 2 < 32) cp_wait<1>(); else cp_wait<0>();
        __syncthreads();
        uint32_t kb = base + A_BUF + (t & 1) * A_BUFSZ;

        float s[8][4];
#pragma unroll
        for (int j = 0; j < 8; ++j)
#pragma unroll
            for (int r = 0; r < 4; ++r) s[j][r] = 0.f;

#pragma unroll
        for (int ks = 0; ks < 4; ++ks) {
            uint32_t ah[4], al[4];
            ldm_x4(aBase + ks * 32,        ah[0], ah[1], ah[2], ah[3]);
            ldm_x4(aBase + A_QL + ks * 32, al[0], al[1], al[2], al[3]);
#pragma unroll
            for (int nb2 = 0; nb2 < 4; ++nb2) {
                uint32_t bAddr = kb + A_KH + (nb2 * 16 + bRowSel) * PQ + bColSel + ks * 32;
                uint32_t h0, h1, h2, h3, u0, u1, u2, u3;
                ldm_x4(bAddr,                 h0, h1, h2, h3);
                ldm_x4(bAddr + (A_KL - A_KH), u0, u1, u2, u3);
                uint32_t bh0[2] = {h0, h1}, bh1[2] = {h2, h3};
                uint32_t bl0[2] = {u0, u1}, bl1[2] = {u2, u3};
                mma16816(s[2*nb2],   ah, bh0); mma16816(s[2*nb2],   ah, bl0);
                mma16816(s[2*nb2],   al, bh0);
                mma16816(s[2*nb2+1], ah, bh1); mma16816(s[2*nb2+1], ah, bl1);
                mma16816(s[2*nb2+1], al, bh1);
            }
        }

        int ktb = t * 64;
        float rm0 = -1e30f, rm1 = -1e30f;
        int i0base = ktb + tc * 2 - qg0 + 2047;
        int i1base = ktb + tc * 2 - qg1 + 2047;
#pragma unroll
        for (int nb = 0; nb < 8; ++nb) {
            int i00 = i0base + nb * 8;
            int i10 = i1base + nb * 8;
            s[nb][0] += bias[i00]; s[nb][1] += bias[i00 + 1];
            s[nb][2] += bias[i10]; s[nb][3] += bias[i10 + 1];
            rm0 = fmaxf(rm0, fmaxf(s[nb][0], s[nb][1]));
            rm1 = fmaxf(rm1, fmaxf(s[nb][2], s[nb][3]));
        }
        rm0 = fmaxf(rm0, __shfl_xor_sync(0xffffffffu, rm0, 1));
        rm0 = fmaxf(rm0, __shfl_xor_sync(0xffffffffu, rm0, 2));
        rm1 = fmaxf(rm1, __shfl_xor_sync(0xffffffffu, rm1, 1));
        rm1 = fmaxf(rm1, __shfl_xor_sync(0xffffffffu, rm1, 2));

        bool upd = __any_sync(0xffffffffu, (rm0 > m0) | (rm1 > m1));
        if (upd) {
            float mn0 = fmaxf(m0, rm0), mn1 = fmaxf(m1, rm1);
            float c0 = ex2f(m0 - mn0), c1 = ex2f(m1 - mn1);
            m0 = mn0; m1 = mn1;
            l0 *= c0; l1 *= c1;
#pragma unroll
            for (int j = 0; j < 8; ++j) {
                acc_o[j][0] *= c0; acc_o[j][1] *= c0;
                acc_o[j][2] *= c1; acc_o[j][3] *= c1;
            }
        }

        float ps0 = 0.f, ps1 = 0.f;
#pragma unroll
        for (int nb = 0; nb < 8; ++nb) {
            s[nb][0] = ex2f(s[nb][0] - m0); s[nb][1] = ex2f(s[nb][1] - m0);
            s[nb][2] = ex2f(s[nb][2] - m1); s[nb][3] = ex2f(s[nb][3] - m1);
            ps0 += s[nb][0] + s[nb][1];
            ps1 += s[nb][2] + s[nb][3];
        }
        ps0 += __shfl_xor_sync(0xffffffffu, ps0, 1);
        ps0 += __shfl_xor_sync(0xffffffffu, ps0, 2);
        ps1 += __shfl_xor_sync(0xffffffffu, ps1, 1);
        ps1 += __shfl_xor_sync(0xffffffffu, ps1, 2);
        l0 += ps0; l1 += ps1;

#pragma unroll
        for (int ks = 0; ks < 4; ++ks) {
            uint32_t ap[4];
            __half2 p0 = __floats2half2_rn(s[2*ks][0],   s[2*ks][1]);
            __half2 p1 = __floats2half2_rn(s[2*ks][2],   s[2*ks][3]);
            __half2 p2 = __floats2half2_rn(s[2*ks+1][0], s[2*ks+1][1]);
            __half2 p3 = __floats2half2_rn(s[2*ks+1][2], s[2*ks+1][3]);
            ap[0] = *(uint32_t*)&p0; ap[1] = *(uint32_t*)&p1;
            ap[2] = *(uint32_t*)&p2; ap[3] = *(uint32_t*)&p3;
#pragma unroll
            for (int db2 = 0; db2 < 4; ++db2) {
                uint32_t vAddr = kb + A_V + (ks * 16 + vRowSel) * PQ + db2 * 32 + vColSel;
                uint32_t h0, h1, h2, h3;
                ldm_x4t(vAddr, h0, h1, h2, h3);
                uint32_t v0[2] = {h0, h1}, v1[2] = {h2, h3};
                mma16816h(acc_o[2*db2],   ap, v0);
                mma16816h(acc_o[2*db2+1], ap, v1);
            }
        }
        __syncthreads();
        if (t + 2 < 32) issue_kv(t + 2, t & 1);
    }

    float inv0 = 1.f / l0, inv1 = 1.f / l1;
#pragma unroll
    for (int db = 0; db < 8; ++db) {
        int dcol = hd * DK + db * 8 + tc * 2;
        size_t o0 = ((size_t)b * S_LEN + qg0) * DM + dcol;
        size_t o1 = ((size_t)b * S_LEN + qg1) * DM + dcol;
        __half2 w0 = __floats2half2_rn(acc_o[db][0] * inv0, acc_o[db][1] * inv0);
        __half2 w1 = __floats2half2_rn(acc_o[db][2] * inv1, acc_o[db][3] * inv1);
        *(uint32_t*)(cf + o0) = *(uint32_t*)&w0;
        *(uint32_t*)(cf + o1) = *(uint32_t*)&w1;
    }
}

// ---------------------------------------------------------------------------
extern "C" void kernel_launch(void* const* d_in, const int* in_sizes, int n_in,
                              void* d_out, int out_size)
{
    const float* hidden  = (const float*)d_in[0];
    const float* wq      = (const float*)d_in[1];
    const float* wk      = (const float*)d_in[2];
    const float* wv      = (const float*)d_in[3];
    const float* wo      = (const float*)d_in[4];
    const float* relbias = (const float*)d_in[5];
    float* out = (float*)d_out;

    __nv_bfloat16 *hhi, *hlo, *whi, *wlo, *qh, *ql, *kh, *kl;
    __half *hf, *wvh, *wvl, *wof, *vf, *cf;
    cudaGetSymbolAddress((void**)&hhi, g_h_hi);
    cudaGetSymbolAddress((void**)&hlo, g_h_lo);
    cudaGetSymbolAddress((void**)&hf,  g_h_f);
    cudaGetSymbolAddress((void**)&whi, g_wt_hi);
    cudaGetSymbolAddress((void**)&wlo, g_wt_lo);
    cudaGetSymbolAddress((void**)&wvh, g_wv_hi);
    cudaGetSymbolAddress((void**)&wvl, g_wv_lo);
    cudaGetSymbolAddress((void**)&wof, g_wo_f);
    cudaGetSymbolAddress((void**)&qh,  g_qh);
    cudaGetSymbolAddress((void**)&ql,  g_ql);
    cudaGetSymbolAddress((void**)&kh,  g_kh);
    cudaGetSymbolAddress((void**)&kl,  g_kl);
    cudaGetSymbolAddress((void**)&vf,  g_vf);
    cudaGetSymbolAddress((void**)&cf,  g_ctx);

    cudaFuncSetAttribute(gemm_qkv, cudaFuncAttributeMaxDynamicSharedMemorySize, QKV_SMEM);
    cudaFuncSetAttribute(gemm_out, cudaFuncAttributeMaxDynamicSharedMemorySize, OUT_SMEM);
    cudaFuncSetAttribute(attn_mma, cudaFuncAttributeMaxDynamicSharedMemorySize, ATT_SMEM);

    prep_all<<<PREP_BLOCKS, 256>>>((const float4*)hidden, hhi, hlo, hf,
                                   wq, wk, wv, wo, whi, wlo, wvh, wvl, wof);

    gemm_qkv<<<dim3(24, 64), 256, QKV_SMEM>>>(hhi, hlo, hf, whi, wlo, wvh, wvl,
                                              qh, ql, kh, kl, vf);

    attn_mma<<<dim3(16, 64), 256, ATT_SMEM>>>(qh, ql, kh, kl, vf, relbias, cf);

    gemm_out<<<dim3(8, 64), 256, OUT_SMEM>>>(cf, wof, out);
}